// round 11
// baseline (speedup 1.0000x reference)
#include <cuda_runtime.h>
#include <cuda_bf16.h>
#include <math_constants.h>
#include <cstdint>

// Problem constants
#define BB 4
#define SS 4096
#define EE 256
#define DD 32

typedef unsigned long long ull;

// ---- packed f32x2 helpers (proj kernel) ----
__device__ __forceinline__ ull ffma2(ull a, ull b, ull c) {
    ull d; asm("fma.rn.f32x2 %0, %1, %2, %3;" : "=l"(d) : "l"(a), "l"(b), "l"(c)); return d;
}
__device__ __forceinline__ ull pack2(float x, float y) {
    ull r; asm("mov.b64 %0, {%1, %2};" : "=l"(r) : "f"(x), "f"(y)); return r;
}
__device__ __forceinline__ float2 unpack2(ull u) {
    float2 v; asm("mov.b64 {%0, %1}, %2;" : "=f"(v.x), "=f"(v.y) : "l"(u)); return v;
}

// ---- bf16 mma.sync m16n8k16 (arch-generic PTX -> HMMA on sm_103) ----
__device__ __forceinline__ void mma_bf16(float c[4], const uint32_t a[4],
                                         uint32_t b0, uint32_t b1) {
    asm volatile(
        "mma.sync.aligned.m16n8k16.row.col.f32.bf16.bf16.f32 "
        "{%0,%1,%2,%3}, {%4,%5,%6,%7}, {%8,%9}, {%0,%1,%2,%3};"
        : "+f"(c[0]), "+f"(c[1]), "+f"(c[2]), "+f"(c[3])
        : "r"(a[0]), "r"(a[1]), "r"(a[2]), "r"(a[3]), "r"(b0), "r"(b1));
}
__device__ __forceinline__ uint32_t cvt_bf2(float a, float b) {
    uint32_t r;
    asm("cvt.rn.satfinite.bf16x2.f32 %0, %1, %2;" : "=r"(r) : "f"(b), "f"(a));
    return r;
}
__device__ __forceinline__ float ex2f(float x) {
    float y; asm("ex2.approx.f32 %0, %1;" : "=f"(y) : "f"(x)); return y;
}
__device__ __forceinline__ void barg(int g) {
    asm volatile("bar.sync %0, %1;" :: "r"(g + 1), "r"(128) : "memory");
}

// Device scratch: hi/lo bf16 splits of projected Q/K/V, [B*S][32] row-major.
// Q is pre-scaled by log2(e) so softmax is a bare ex2.
__device__ __nv_bfloat16 g_qh[BB * SS * DD], g_ql[BB * SS * DD];
__device__ __nv_bfloat16 g_kh[BB * SS * DD], g_kl[BB * SS * DD];
__device__ __nv_bfloat16 g_vh[BB * SS * DD], g_vl[BB * SS * DD];

// ---------------------------------------------------------------------------
// Projection: q/k/v = x @ W (fp32 FFMA2), outputs split to bf16 hi/lo.
// ---------------------------------------------------------------------------
__global__ __launch_bounds__(256, 1) void proj_kernel(
    const float* __restrict__ x,
    const float* __restrict__ Wq,
    const float* __restrict__ Wk,
    const float* __restrict__ Wv)
{
    __shared__ float xs[32 * EE];
    const int row0 = blockIdx.x * 32;
    const int tid = threadIdx.x;

    const float4* xg = (const float4*)(x + (size_t)row0 * EE);
    float4* xs4 = (float4*)xs;
#pragma unroll
    for (int i = 0; i < 8; i++) xs4[tid + i * 256] = xg[tid + i * 256];
    __syncthreads();

    const int col = tid & 31;
    const int rg  = tid >> 5;

    ull aq2[4], ak2[4], av2[4];
#pragma unroll
    for (int rr = 0; rr < 4; rr++) { aq2[rr] = 0; ak2[rr] = 0; av2[rr] = 0; }

#pragma unroll 2
    for (int e = 0; e < EE; e += 2) {
        const ull wq2 = pack2(__ldg(&Wq[e * DD + col]), __ldg(&Wq[(e + 1) * DD + col]));
        const ull wk2 = pack2(__ldg(&Wk[e * DD + col]), __ldg(&Wk[(e + 1) * DD + col]));
        const ull wv2 = pack2(__ldg(&Wv[e * DD + col]), __ldg(&Wv[(e + 1) * DD + col]));
#pragma unroll
        for (int rr = 0; rr < 4; rr++) {
            const ull xv2 = *(const ull*)&xs[(rg * 4 + rr) * EE + e];
            aq2[rr] = ffma2(xv2, wq2, aq2[rr]);
            ak2[rr] = ffma2(xv2, wk2, ak2[rr]);
            av2[rr] = ffma2(xv2, wv2, av2[rr]);
        }
    }

#pragma unroll
    for (int rr = 0; rr < 4; rr++) {
        const int r = row0 + rg * 4 + rr;
        const float2 q2 = unpack2(aq2[rr]);
        const float2 k2 = unpack2(ak2[rr]);
        const float2 v2 = unpack2(av2[rr]);
        // fold log2(e) into q so exp(s) == ex2(q'.k)
        const float q = (q2.x + q2.y) * 1.4426950408889634f;
        const float k = k2.x + k2.y, v = v2.x + v2.y;
        const int o = r * DD + col;

        const __nv_bfloat16 qh = __float2bfloat16(q);
        g_qh[o] = qh; g_ql[o] = __float2bfloat16(q - __bfloat162float(qh));
        const __nv_bfloat16 kh = __float2bfloat16(k);
        g_kh[o] = kh; g_kl[o] = __float2bfloat16(k - __bfloat162float(kh));
        const __nv_bfloat16 vh = __float2bfloat16(v);
        g_vh[o] = vh; g_vl[o] = __float2bfloat16(v - __bfloat162float(vh));
    }
}

// ---------------------------------------------------------------------------
// HMMA flash attention, TWO warp groups on interleaved chunks.
// CTA = 256 threads. Group g = warps [4g,4g+4): all 128 queries (32 q/warp),
// key-chunks n = g, g+2, ... (32 each). Per-group double-buffered K/V smem,
// group-scoped bar.sync -> groups free-run out of phase; one group's mma
// issue fills the tensor pipe during the other's softmax. Partial acc and
// denominators merged through smem at the end.
// Split-bf16 (hi+lo) on both GEMMs (3 mmas/product); no max-shift.
//
// SMEM words (uint32 = bf16x2):
//   Q   : [0, 4096)       hi @0, lo @2048; row r -> r*16 + d2
//   K   : [4096, 14336)   4 buffers (grp*2+d)*2560: hi 64x20-stride, lo +1280
//   V   : [14336, 24576)  4 buffers: hi 32x40-stride {2k2,2k2+1} pairs, lo +1280
//   EX  : aliases K after the loops: acc @4096 (128x32 f32), l @8192 (128 f32)
// ---------------------------------------------------------------------------
#define QPH_W 0
#define QPL_W 2048
#define KBASE_W 4096
#define VBASE_W 14336
#define EXA_W 4096
#define EXL_W 8192
#define SMEM_BYTES (24576 * 4)

__global__ __launch_bounds__(256, 1) void attn_mma(float* __restrict__ out)
{
    extern __shared__ uint32_t smw[];
    float* fsm = (float*)smw;
    const int tid  = threadIdx.x;
    const int wid  = tid >> 5, lane = tid & 31;
    const int gid  = lane >> 2, tig = lane & 3;
    const int grp  = wid >> 2;          // 0 or 1
    const int w4   = wid & 3;           // warp within group
    const int tg   = tid & 127;         // thread within group
    const int b    = blockIdx.y;
    const int q0   = blockIdx.x * 128;
    const int qbase = w4 * 32;

    const __nv_bfloat16* khb = g_kh + (size_t)b * SS * DD;
    const __nv_bfloat16* klb = g_kl + (size_t)b * SS * DD;
    const __nv_bfloat16* vhb = g_vh + (size_t)b * SS * DD;
    const __nv_bfloat16* vlb = g_vl + (size_t)b * SS * DD;

    // ---- one-time Q tile load (all 256 threads) ----
#pragma unroll
    for (int it = 0; it < 4; it++) {
        const int u = tid + it * 256;
        const int split = u >> 9, r = (u >> 2) & 127, c4 = u & 3;
        const __nv_bfloat16* src = split ? g_ql : g_qh;
        const uint4 d = *(const uint4*)(src + (size_t)(b * SS + q0 + r) * DD + c4 * 8);
        *(uint4*)&smw[(split ? QPL_W : QPH_W) + r * 16 + c4 * 4] = d;
    }
    __syncthreads();

    // ---- Q fragments: [split][mt][kt][4] ----
    uint32_t qf[2][2][2][4];
#pragma unroll
    for (int s = 0; s < 2; s++)
#pragma unroll
        for (int mt = 0; mt < 2; mt++)
#pragma unroll
            for (int kt = 0; kt < 2; kt++) {
                const int base = s ? QPL_W : QPH_W;
                const int row = qbase + mt * 16;
                qf[s][mt][kt][0] = smw[base + (row + gid) * 16 + kt * 8 + tig];
                qf[s][mt][kt][1] = smw[base + (row + gid + 8) * 16 + kt * 8 + tig];
                qf[s][mt][kt][2] = smw[base + (row + gid) * 16 + kt * 8 + tig + 4];
                qf[s][mt][kt][3] = smw[base + (row + gid + 8) * 16 + kt * 8 + tig + 4];
            }

    // ---- per-thread staged-load coordinates (group-local, 128 threads) ----
    int k_off[4], k_drel[4];
    const __nv_bfloat16* k_src[4];
#pragma unroll
    for (int it = 0; it < 4; it++) {
        const int u = tg + it * 128;
        const int split = u >> 8, r = (u >> 2) & 63, c4 = u & 3;
        k_src[it] = split ? klb : khb;
        k_off[it] = r * DD + c4 * 8;
        k_drel[it] = (split ? 1280 : 0) + r * 20 + c4 * 4;
    }
    int v_off[2], v_drel[2];
    const __nv_bfloat16* v_src[2];
#pragma unroll
    for (int it = 0; it < 2; it++) {
        const int u = tg + it * 128;
        const int split = (u >> 7) & 1, k2 = (u >> 2) & 31, nb = u & 3;
        v_src[it] = split ? vlb : vhb;
        v_off[it] = k2 * 2 * DD + nb * 8;
        v_drel[it] = (split ? 1280 : 0) + k2 * 40 + nb * 8;
    }

    // ---- prologue: load chunk 'grp' into buffer (grp*2 + 0) ----
    uint4 kreg[4], va[2], vbr[2];
    {
        const int kc = grp * 64 * DD;
#pragma unroll
        for (int it = 0; it < 4; it++) kreg[it] = *(const uint4*)(k_src[it] + kc + k_off[it]);
#pragma unroll
        for (int it = 0; it < 2; it++) {
            va[it]  = *(const uint4*)(v_src[it] + kc + v_off[it]);
            vbr[it] = *(const uint4*)(v_src[it] + kc + v_off[it] + DD);
        }
        const int kb = KBASE_W + (grp * 2) * 2560;
        const int vw = VBASE_W + (grp * 2) * 2560;
#pragma unroll
        for (int it = 0; it < 4; it++) *(uint4*)&smw[kb + k_drel[it]] = kreg[it];
#pragma unroll
        for (int it = 0; it < 2; it++) {
            const uint32_t* A = (const uint32_t*)&va[it];
            const uint32_t* B = (const uint32_t*)&vbr[it];
            uint32_t w[8];
#pragma unroll
            for (int j = 0; j < 4; j++) {
                w[2 * j]     = __byte_perm(A[j], B[j], 0x5410);
                w[2 * j + 1] = __byte_perm(A[j], B[j], 0x7632);
            }
            *(uint4*)&smw[vw + v_drel[it]]     = *(uint4*)&w[0];
            *(uint4*)&smw[vw + v_drel[it] + 4] = *(uint4*)&w[4];
        }
    }
    barg(grp);

    float acc[2][4][4];
#pragma unroll
    for (int mt = 0; mt < 2; mt++)
#pragma unroll
        for (int i = 0; i < 4; i++)
#pragma unroll
            for (int j = 0; j < 4; j++) acc[mt][i][j] = 0.f;
    float l[2][2] = {{0.f, 0.f}, {0.f, 0.f}};

    for (int i = 0; i < 32; i++) {
        const int d = i & 1, bi = grp * 2 + d;
        const int kbh = KBASE_W + bi * 2560, kbl = kbh + 1280;
        const int vbh = VBASE_W + bi * 2560, vbl = vbh + 1280;
        const bool pre = (i < 31);

        // ---- QK: S(32q x 64k), B-fragments shared across mt ----
        float c[2][8][4];
#pragma unroll
        for (int mt = 0; mt < 2; mt++)
#pragma unroll
            for (int nt = 0; nt < 8; nt++)
#pragma unroll
                for (int j = 0; j < 4; j++) c[mt][nt][j] = 0.f;

#pragma unroll
        for (int kt = 0; kt < 2; kt++)
#pragma unroll
            for (int nt = 0; nt < 8; nt++) {
                const int w0 = (nt * 8 + gid) * 20 + kt * 8 + tig;
                const uint32_t kh0 = smw[kbh + w0], kh1 = smw[kbh + w0 + 4];
                const uint32_t kl0 = smw[kbl + w0], kl1 = smw[kbl + w0 + 4];
#pragma unroll
                for (int mt = 0; mt < 2; mt++) {
                    mma_bf16(c[mt][nt], qf[0][mt][kt], kh0, kh1);
                    mma_bf16(c[mt][nt], qf[0][mt][kt], kl0, kl1);
                    mma_bf16(c[mt][nt], qf[1][mt][kt], kh0, kh1);
                }
            }

        // ---- stage chunk n+2 (LDG latency covered by softmax+PV) ----
        if (pre) {
            const int kc = (grp + 2 * (i + 1)) * 64 * DD;
#pragma unroll
            for (int it = 0; it < 4; it++) kreg[it] = *(const uint4*)(k_src[it] + kc + k_off[it]);
#pragma unroll
            for (int it = 0; it < 2; it++) {
                va[it]  = *(const uint4*)(v_src[it] + kc + v_off[it]);
                vbr[it] = *(const uint4*)(v_src[it] + kc + v_off[it] + DD);
            }
        }

        // ---- softmax (bare ex2; log2e folded into Q) + repack to A-frags ----
        uint32_t aph[2][4][4], apl[2][4][4];
#pragma unroll
        for (int mt = 0; mt < 2; mt++)
#pragma unroll
            for (int nt = 0; nt < 8; nt++) {
                const float p0 = ex2f(c[mt][nt][0]);
                const float p1 = ex2f(c[mt][nt][1]);
                const float p2 = ex2f(c[mt][nt][2]);
                const float p3 = ex2f(c[mt][nt][3]);
                l[mt][0] += p0 + p1;
                l[mt][1] += p2 + p3;
                const uint32_t h01 = cvt_bf2(p0, p1);
                const uint32_t h23 = cvt_bf2(p2, p3);
                const float r0 = p0 - __uint_as_float(h01 << 16);
                const float r1 = p1 - __uint_as_float(h01 & 0xFFFF0000u);
                const float r2 = p2 - __uint_as_float(h23 << 16);
                const float r3 = p3 - __uint_as_float(h23 & 0xFFFF0000u);
                const uint32_t q01 = cvt_bf2(r0, r1);
                const uint32_t q23 = cvt_bf2(r2, r3);
                const int kt2 = nt >> 1, hi = (nt & 1) * 2;
                aph[mt][kt2][hi]     = h01; aph[mt][kt2][hi + 1] = h23;
                apl[mt][kt2][hi]     = q01; apl[mt][kt2][hi + 1] = q23;
            }

        // ---- PV: O(32q x 32d), B-fragments shared across mt ----
#pragma unroll
        for (int kt2 = 0; kt2 < 4; kt2++)
#pragma unroll
            for (int nt2 = 0; nt2 < 4; nt2++) {
                const int w0 = (kt2 * 8 + tig) * 40 + nt2 * 8 + gid;
                const uint32_t vh0 = smw[vbh + w0], vh1 = smw[vbh + w0 + 160];
                const uint32_t vl0 = smw[vbl + w0], vl1 = smw[vbl + w0 + 160];
#pragma unroll
                for (int mt = 0; mt < 2; mt++) {
                    mma_bf16(acc[mt][nt2], aph[mt][kt2], vh0, vh1);
                    mma_bf16(acc[mt][nt2], aph[mt][kt2], vl0, vl1);
                    mma_bf16(acc[mt][nt2], apl[mt][kt2], vh0, vh1);
                }
            }

        // ---- commit staged chunk to the other buffer ----
        if (pre) {
            const int kb2 = KBASE_W + (grp * 2 + (d ^ 1)) * 2560;
            const int vw2 = VBASE_W + (grp * 2 + (d ^ 1)) * 2560;
#pragma unroll
            for (int it = 0; it < 4; it++) *(uint4*)&smw[kb2 + k_drel[it]] = kreg[it];
#pragma unroll
            for (int it = 0; it < 2; it++) {
                const uint32_t* A = (const uint32_t*)&va[it];
                const uint32_t* B = (const uint32_t*)&vbr[it];
                uint32_t w[8];
#pragma unroll
                for (int j = 0; j < 4; j++) {
                    w[2 * j]     = __byte_perm(A[j], B[j], 0x5410);
                    w[2 * j + 1] = __byte_perm(A[j], B[j], 0x7632);
                }
                *(uint4*)&smw[vw2 + v_drel[it]]     = *(uint4*)&w[0];
                *(uint4*)&smw[vw2 + v_drel[it] + 4] = *(uint4*)&w[4];
            }
        }
        barg(grp);   // group-scoped: the other group free-runs
    }

    // ---- reduce l over the 4 tig lanes (both groups) ----
#pragma unroll
    for (int mt = 0; mt < 2; mt++)
#pragma unroll
        for (int h = 0; h < 2; h++) {
            l[mt][h] += __shfl_xor_sync(0xffffffffu, l[mt][h], 1, 4);
            l[mt][h] += __shfl_xor_sync(0xffffffffu, l[mt][h], 2, 4);
        }

    __syncthreads();   // both groups done; K/V smem now dead -> reuse as EX

    if (grp == 0) {
#pragma unroll
        for (int mt = 0; mt < 2; mt++) {
            const int r0 = qbase + mt * 16 + gid, r8 = r0 + 8;
#pragma unroll
            for (int nt2 = 0; nt2 < 4; nt2++) {
                *(float2*)&fsm[EXA_W + r0 * 32 + nt2 * 8 + tig * 2] =
                    make_float2(acc[mt][nt2][0], acc[mt][nt2][1]);
                *(float2*)&fsm[EXA_W + r8 * 32 + nt2 * 8 + tig * 2] =
                    make_float2(acc[mt][nt2][2], acc[mt][nt2][3]);
            }
            fsm[EXL_W + r0] = l[mt][0];
            fsm[EXL_W + r8] = l[mt][1];
        }
    }
    __syncthreads();
    if (grp == 1) {
        const float scaling = 0.17677669529663687f;  // 32^-0.5 post-softmax
#pragma unroll
        for (int mt = 0; mt < 2; mt++) {
            const int r0 = qbase + mt * 16 + gid, r8 = r0 + 8;
            const float inv0 = scaling / (fsm[EXL_W + r0] + l[mt][0]);
            const float inv8 = scaling / (fsm[EXL_W + r8] + l[mt][1]);
#pragma unroll
            for (int nt2 = 0; nt2 < 4; nt2++) {
                const float2 eA0 = *(const float2*)&fsm[EXA_W + r0 * 32 + nt2 * 8 + tig * 2];
                const float2 eA8 = *(const float2*)&fsm[EXA_W + r8 * 32 + nt2 * 8 + tig * 2];
                float2 o0, o8;
                o0.x = (eA0.x + acc[mt][nt2][0]) * inv0;
                o0.y = (eA0.y + acc[mt][nt2][1]) * inv0;
                o8.x = (eA8.x + acc[mt][nt2][2]) * inv8;
                o8.y = (eA8.y + acc[mt][nt2][3]) * inv8;
                *(float2*)(out + (size_t)(b * SS + q0 + r0) * DD + nt2 * 8 + tig * 2) = o0;
                *(float2*)(out + (size_t)(b * SS + q0 + r8) * DD + nt2 * 8 + tig * 2) = o8;
            }
        }
    }
}

// ---------------------------------------------------------------------------
extern "C" void kernel_launch(void* const* d_in, const int* in_sizes, int n_in,
                              void* d_out, int out_size)
{
    const float* x  = (const float*)d_in[0];
    const float* Wq = (const float*)d_in[1];
    const float* Wk = (const float*)d_in[2];
    const float* Wv = (const float*)d_in[3];
    float* out = (float*)d_out;

    proj_kernel<<<(BB * SS) / 32, 256>>>(x, Wq, Wk, Wv);

    cudaFuncSetAttribute(attn_mma, cudaFuncAttributeMaxDynamicSharedMemorySize, SMEM_BYTES);
    dim3 grid(SS / 128, BB);
    attn_mma<<<grid, 256, SMEM_BYTES>>>(out);
}